// round 14
// baseline (speedup 1.0000x reference)
#include <cuda_runtime.h>
#include <cuda_fp16.h>
#include <cstdint>

// ---------------------------------------------------------------------------
// Problem constants
// ---------------------------------------------------------------------------
#define NC      100     // NUM_CLASSES
#define DDIM    512     // feature dim
#define SSPEC   10      // specialists
#define KCLUS   10      // cluster size
#define NPAD    104     // padded N (13 x n8 tiles)
#define NTILES  13
#define TILE_M  128
#define KC      64      // K per chunk
#define NCHUNK  (DDIM / KC)   // 8
#define THREADS 256

// SMEM: 1KB align slack + 2 x 32KB fp32 staging + 2 x 16KB fp16 A tile = 97KB
#define XS_BUF  32768
#define A_OFF   (1024 + 2 * XS_BUF)
#define A_BUF   16384
#define SMEM_DYN (1024 + 2 * XS_BUF + 2 * A_BUF)

// ---------------------------------------------------------------------------
// Device scratch
// ---------------------------------------------------------------------------
__device__ __align__(16) float g_b1[NC];
__device__ __align__(16) float g_beff[NPAD];
__device__ int g_cls_s[NC];
__device__ int g_cls_k[NC];
// B fragments, single fp16 plane, native m16n8k16 per-lane layout:
// [ks 0..31][nt 0..12][lane 0..31] -> uint2 {b0, b1}
__device__ __align__(16) uint2 g_Bfrag[32 * NTILES * 32];

// ---------------------------------------------------------------------------
// Helpers
// ---------------------------------------------------------------------------
__device__ __forceinline__ uint32_t cvta_smem(const void* p) {
    return (uint32_t)__cvta_generic_to_shared(p);
}
__device__ __forceinline__ uint32_t sw128(uint32_t off) {
    return off ^ ((off >> 3) & 0x70);
}
__device__ __forceinline__ void cp_async16(uint32_t dst, const void* src) {
    asm volatile("cp.async.cg.shared.global [%0], [%1], 16;" :: "r"(dst), "l"(src));
}
__device__ __forceinline__ void ldmatrix_x4(uint32_t* r, uint32_t addr) {
    asm volatile("ldmatrix.sync.aligned.m8n8.x4.shared.b16 {%0,%1,%2,%3}, [%4];"
                 : "=r"(r[0]), "=r"(r[1]), "=r"(r[2]), "=r"(r[3]) : "r"(addr));
}
__device__ __forceinline__ void mma_f16(float* d, const uint32_t* a, uint2 b) {
    asm volatile(
        "mma.sync.aligned.m16n8k16.row.col.f32.f16.f16.f32 "
        "{%0,%1,%2,%3}, {%4,%5,%6,%7}, {%8,%9}, {%0,%1,%2,%3};"
        : "+f"(d[0]), "+f"(d[1]), "+f"(d[2]), "+f"(d[3])
        : "r"(a[0]), "r"(a[1]), "r"(a[2]), "r"(a[3]), "r"(b.x), "r"(b.y));
}

// ---------------------------------------------------------------------------
// prepA: cluster map + folded first-layer bias g_b1
// ---------------------------------------------------------------------------
__global__ void prepA_kernel(const int* __restrict__ clusters,
                             const float* __restrict__ bg,
                             const float* __restrict__ bs) {
    int t = threadIdx.x;
    if (t < NC) {
        int s = t / KCLUS, k = t % KCLUS;
        int c = clusters[t];
        g_cls_s[c] = s;
        g_cls_k[c] = k;
    }
    __syncthreads();
    if (t < NC) {
        int s = g_cls_s[t], k = g_cls_k[t];
        float bsum = 0.f;
        #pragma unroll
        for (int sp = 0; sp < SSPEC; sp++) bsum += bs[sp * (KCLUS + 1) + KCLUS];
        g_b1[t] = bg[t] + bs[s * (KCLUS + 1) + k] +
                  (bsum - bs[s * (KCLUS + 1) + KCLUS]) * (1.0f / (NC - KCLUS));
    }
}

// ---------------------------------------------------------------------------
// prepC (fused): fold W1[d][:] on the fly, then Weff[d][n] = W1[d]·Wc[:,n],
// stored as fp16 directly into the mma fragment image.
// 512 blocks (d) x 104 threads (n).
// ---------------------------------------------------------------------------
__global__ void prepC_kernel(const float* __restrict__ Wg,
                             const float* __restrict__ Ws,
                             const float* __restrict__ Wc) {
    __shared__ float w1row[NC];
    int d = blockIdx.x;
    int n = threadIdx.x;

    float dsum = 0.f;
    #pragma unroll
    for (int sp = 0; sp < SSPEC; sp++)
        dsum += Ws[sp * DDIM * (KCLUS + 1) + d * (KCLUS + 1) + KCLUS];
    if (n < NC) {
        int s = g_cls_s[n], k = g_cls_k[n];
        w1row[n] = Wg[d * NC + n] + Ws[s * DDIM * (KCLUS + 1) + d * (KCLUS + 1) + k] +
                   (dsum - Ws[s * DDIM * (KCLUS + 1) + d * (KCLUS + 1) + KCLUS]) *
                       (1.0f / (NC - KCLUS));
    }
    __syncthreads();

    float acc = 0.f;
    if (n < NC) {
        #pragma unroll 4
        for (int t = 0; t < NC; t++)
            acc += w1row[t] * Wc[t * NC + n];
    }
    // fragment index for element (d, n):
    //   ks = d>>4, r = d&15, reg = r>>3, lane = (n&7)*4 + ((r&7)>>1), par = d&1
    int ks = d >> 4, r = d & 15;
    int lane = ((n & 7) << 2) | ((r & 7) >> 1);
    int idx = (((ks * NTILES + (n >> 3)) * 32 + lane) << 2) | ((r >> 3) << 1) | (d & 1);
    unsigned short* bu = (unsigned short*)g_Bfrag;
    bu[idx] = __half_as_ushort(__float2half_rn(acc));
}

// ---------------------------------------------------------------------------
// prepD: beff = b1 @ Wc + bc  (one block per output col, warp-parallel dot)
// ---------------------------------------------------------------------------
__global__ void prepD_kernel(const float* __restrict__ Wc,
                             const float* __restrict__ bc) {
    int c = blockIdx.x;
    int lane = threadIdx.x;
    float s = 0.f;
    if (c < NC) {
        #pragma unroll
        for (int k = lane; k < NC; k += 32)
            s += g_b1[k] * Wc[k * NC + c];
    }
    #pragma unroll
    for (int o = 16; o > 0; o >>= 1)
        s += __shfl_xor_sync(0xFFFFFFFFu, s, o);
    if (lane == 0)
        g_beff[c] = (c < NC) ? (s + bc[c]) : 0.f;
}

// ---------------------------------------------------------------------------
// Main GEMM: out = relu(x @ Weff + beff), fp16 mma.sync, single W plane.
// TILE_M=128, 8 warps: warp grid 4(M) x 2(N); warp tile m32 x n56/n48.
// R14: phases merged — convert(ch+1) interleaved into the MMA phase of ch
// (disjoint A buffers), staging 2 chunks deep, B fragments register-pipelined
// seamlessly across chunk boundaries (prefetch gks+1 every step).
// One barrier per chunk separates convert(k) writes from MMA(k) reads.
// ---------------------------------------------------------------------------
__global__ __launch_bounds__(THREADS, 2)
void gemm_main_kernel(const float* __restrict__ x, float* __restrict__ out) {
    extern __shared__ unsigned char smem_raw[];
    uint32_t sb0 = cvta_smem(smem_raw);
    uint32_t sb = (sb0 + 1023u) & ~1023u;
    unsigned char* smem = smem_raw + (sb - sb0);

    const uint32_t XS = sb + 1024;          // 2 x [128][64] f32 staging
    float* xs = (float*)(smem + 1024);

    const int tid  = threadIdx.x;
    const int wid  = tid >> 5;
    const int lane = tid & 31;
    const int wm   = wid >> 1;              // 0..3 -> m32 tile
    const int wn   = wid & 1;               // 0..1 -> n half (7 / 6 tiles)
    const int jmax = wn ? 6 : 7;

    const int rbase = tid >> 4;             // row for i=0 (0..15)
    const int q     = tid & 15;             // float4 column index

    const float* xt = x + (size_t)blockIdx.x * TILE_M * DDIM;
    const float* xrow = xt + (size_t)rbase * DDIM + q * 4;

    float acc[2][7][4];
    #pragma unroll
    for (int mt = 0; mt < 2; mt++)
        #pragma unroll
        for (int j = 0; j < 7; j++)
            #pragma unroll
            for (int qq = 0; qq < 4; qq++) acc[mt][j][qq] = 0.f;

    // ---- prologue: stage chunks 0 and 1, convert chunk 0 ----
    #pragma unroll
    for (int i = 0; i < 8; i++) {
        int r = rbase + i * 16;
        cp_async16(XS + (uint32_t)(r * 64 + q * 4) * 4,
                   xrow + (size_t)i * 16 * DDIM);
    }
    asm volatile("cp.async.commit_group;" ::: "memory");
    {
        const float* xn = xrow + KC;
        #pragma unroll
        for (int i = 0; i < 8; i++) {
            int r = rbase + i * 16;
            cp_async16(XS + XS_BUF + (uint32_t)(r * 64 + q * 4) * 4,
                       xn + (size_t)i * 16 * DDIM);
        }
    }
    asm volatile("cp.async.commit_group;" ::: "memory");
    asm volatile("cp.async.wait_group 1;" ::: "memory");   // chunk 0 staged

    // convert chunk 0 -> A[0]
    #pragma unroll
    for (int i = 0; i < 8; i++) {
        int r = rbase + i * 16;
        float4 v = *(const float4*)(xs + r * 64 + q * 4);
        __half2 p01 = __floats2half2_rn(v.x, v.y);
        __half2 p23 = __floats2half2_rn(v.z, v.w);
        uint32_t off = sw128((uint32_t)(r * 128 + q * 8));
        *(uint2*)(smem + A_OFF + off) =
            make_uint2(*(uint32_t*)&p01, *(uint32_t*)&p23);
    }

    // seamless B pipeline: preload gks=0 fragments
    uint2 bcur[7];
    {
        const uint2* bp = g_Bfrag + (size_t)(wn * 7) * 32 + lane;
        #pragma unroll
        for (int j = 0; j < 7; j++)
            if (j < jmax) bcur[j] = bp[j * 32];
    }

    // one MMA k16 step: ldmatrix A, prefetch B(gks+1), 14 HMMA, rotate B regs
    #define MMA_STEP(ks_)                                                      \
    do {                                                                       \
        uint32_t a_[2][4];                                                     \
        _Pragma("unroll")                                                      \
        for (int mt = 0; mt < 2; mt++) {                                       \
            int row_  = wm * 32 + mt * 16 + ((lane >> 3) & 1) * 8 + (lane & 7);\
            int half_ = lane >> 4;                                             \
            uint32_t off_ = sw128((uint32_t)(row_ * 128 + (ks_) * 32 + half_ * 16)); \
            ldmatrix_x4(a_[mt], AT + off_);                                    \
        }                                                                      \
        uint2 bnxt_[7];                                                        \
        int gnext_ = ch * 4 + (ks_) + 1;                                       \
        if (gnext_ < 32) {                                                     \
            const uint2* bp_ = g_Bfrag + (size_t)(gnext_ * NTILES + wn * 7) * 32 + lane; \
            _Pragma("unroll")                                                  \
            for (int j = 0; j < 7; j++)                                        \
                if (j < jmax) bnxt_[j] = bp_[j * 32];                          \
        }                                                                      \
        _Pragma("unroll")                                                      \
        for (int j = 0; j < 7; j++) {                                          \
            if (j < jmax) {                                                    \
                mma_f16(acc[0][j], a_[0], bcur[j]);                            \
                mma_f16(acc[1][j], a_[1], bcur[j]);                            \
            }                                                                  \
        }                                                                      \
        if (gnext_ < 32) {                                                     \
            _Pragma("unroll")                                                  \
            for (int j = 0; j < 7; j++)                                        \
                if (j < jmax) bcur[j] = bnxt_[j];                              \
        }                                                                      \
    } while (0)

    for (int ch = 0; ch < NCHUNK; ch++) {
        // barrier separates convert(ch) [prev iter / prologue] from MMA(ch),
        // and MMA(ch-1) from convert(ch+1) A-buffer reuse.
        __syncthreads();
        const uint32_t AT = sb + A_OFF + (uint32_t)(ch & 1) * A_BUF;

        // issue staging for ch+2 (overwrites staging[ch&1], whose convert(ch)
        // reads completed before this iteration's barrier)
        if (ch + 2 < NCHUNK) {
            uint32_t bufoff = (uint32_t)(ch & 1) * XS_BUF;
            const float* xn = xrow + (ch + 2) * KC;
            #pragma unroll
            for (int i = 0; i < 8; i++) {
                int r = rbase + i * 16;
                cp_async16(XS + bufoff + (uint32_t)(r * 64 + q * 4) * 4,
                           xn + (size_t)i * 16 * DDIM);
            }
            asm volatile("cp.async.commit_group;" ::: "memory");
        }

        MMA_STEP(0);
        MMA_STEP(1);

        // wait chunk ch+1 staged, convert it into A[(ch+1)&1]
        // (disjoint from the A[ch&1] tile being read by this chunk's MMAs)
        if (ch + 1 < NCHUNK) {
            if (ch + 2 < NCHUNK) {
                asm volatile("cp.async.wait_group 1;" ::: "memory");
            } else {
                asm volatile("cp.async.wait_group 0;" ::: "memory");
            }
            const float* xb = xs + ((ch + 1) & 1) * (XS_BUF / 4);
            uint32_t abase = A_OFF + (uint32_t)((ch + 1) & 1) * A_BUF;
            #pragma unroll
            for (int i = 0; i < 8; i++) {
                int r = rbase + i * 16;
                float4 v = *(const float4*)(xb + r * 64 + q * 4);
                __half2 p01 = __floats2half2_rn(v.x, v.y);
                __half2 p23 = __floats2half2_rn(v.z, v.w);
                uint32_t off = sw128((uint32_t)(r * 128 + q * 8));
                *(uint2*)(smem + abase + off) =
                    make_uint2(*(uint32_t*)&p01, *(uint32_t*)&p23);
            }
        }

        MMA_STEP(2);
        MMA_STEP(3);
    }
    #undef MMA_STEP

    // ---- epilogue: bias + relu + direct STG ----
    const int g  = lane >> 2;
    const int tq = lane & 3;
    const int mrow = blockIdx.x * TILE_M + wm * 32;
    #pragma unroll
    for (int mt = 0; mt < 2; mt++) {
        #pragma unroll
        for (int j = 0; j < 7; j++) {
            if (j < jmax) {
                int c = wn * 56 + j * 8 + tq * 2;
                if (c < NC) {
                    float2 bv = *(const float2*)&g_beff[c];
                    int r0 = mrow + mt * 16 + g;
                    float v0 = acc[mt][j][0] + bv.x;
                    float v1 = acc[mt][j][1] + bv.y;
                    float v2 = acc[mt][j][2] + bv.x;
                    float v3 = acc[mt][j][3] + bv.y;
                    float2 o0 = make_float2(v0 > 0.f ? v0 : 0.f, v1 > 0.f ? v1 : 0.f);
                    float2 o1 = make_float2(v2 > 0.f ? v2 : 0.f, v3 > 0.f ? v3 : 0.f);
                    *(float2*)(out + (size_t)r0 * NC + c)       = o0;
                    *(float2*)(out + (size_t)(r0 + 8) * NC + c) = o1;
                }
            }
        }
    }
}

// ---------------------------------------------------------------------------
// Launch
// ---------------------------------------------------------------------------
extern "C" void kernel_launch(void* const* d_in, const int* in_sizes, int n_in,
                              void* d_out, int out_size) {
    const float* x        = (const float*)d_in[0];
    const float* Wg       = (const float*)d_in[1];
    const float* bg       = (const float*)d_in[2];
    const float* Ws       = (const float*)d_in[3];
    const float* bs       = (const float*)d_in[4];
    const float* Wc       = (const float*)d_in[5];
    const float* bc       = (const float*)d_in[6];
    const int*   clusters = (const int*)d_in[7];
    float* out = (float*)d_out;

    int Btot = in_sizes[0] / DDIM;      // 131072
    int grid = Btot / TILE_M;           // 1024

    cudaFuncSetAttribute(gemm_main_kernel,
                         cudaFuncAttributeMaxDynamicSharedMemorySize, SMEM_DYN);

    prepA_kernel<<<1, 128>>>(clusters, bg, bs);
    prepD_kernel<<<NPAD, 32>>>(Wc, bc);
    prepC_kernel<<<DDIM, NPAD>>>(Wg, Ws, Wc);
    gemm_main_kernel<<<grid, THREADS, SMEM_DYN>>>(x, out);
}

// round 15
// speedup vs baseline: 1.3725x; 1.3725x over previous
#include <cuda_runtime.h>
#include <cuda_fp16.h>
#include <cstdint>

// ---------------------------------------------------------------------------
// Problem constants
// ---------------------------------------------------------------------------
#define NC      100     // NUM_CLASSES
#define DDIM    512     // feature dim
#define SSPEC   10      // specialists
#define KCLUS   10      // cluster size
#define NPAD    104     // padded N (13 x n8 tiles)
#define NTILES  13
#define TILE_M  128
#define KC      64      // K per chunk
#define NCHUNK  (DDIM / KC)   // 8
#define THREADS 256

// SMEM: 1KB align slack + 2 x 32KB fp32 staging + 2 x 16KB fp16 A tile = 97KB
#define XS_BUF  32768
#define A_OFF   (1024 + 2 * XS_BUF)
#define A_BUF   16384
#define SMEM_DYN (1024 + 2 * XS_BUF + 2 * A_BUF)

// ---------------------------------------------------------------------------
// Device scratch
// ---------------------------------------------------------------------------
__device__ __align__(16) float g_b1[NC];
__device__ __align__(16) float g_beff[NPAD];
__device__ int g_cls_s[NC];
__device__ int g_cls_k[NC];
// B fragments, single fp16 plane, native m16n8k16 per-lane layout:
// [ks 0..31][nt 0..12][lane 0..31] -> uint2 {b0, b1}
__device__ __align__(16) uint2 g_Bfrag[32 * NTILES * 32];

// ---------------------------------------------------------------------------
// Helpers
// ---------------------------------------------------------------------------
__device__ __forceinline__ uint32_t cvta_smem(const void* p) {
    return (uint32_t)__cvta_generic_to_shared(p);
}
__device__ __forceinline__ uint32_t sw128(uint32_t off) {
    return off ^ ((off >> 3) & 0x70);
}
__device__ __forceinline__ void cp_async16(uint32_t dst, const void* src) {
    asm volatile("cp.async.cg.shared.global [%0], [%1], 16;" :: "r"(dst), "l"(src));
}
__device__ __forceinline__ void ldmatrix_x4(uint32_t* r, uint32_t addr) {
    asm volatile("ldmatrix.sync.aligned.m8n8.x4.shared.b16 {%0,%1,%2,%3}, [%4];"
                 : "=r"(r[0]), "=r"(r[1]), "=r"(r[2]), "=r"(r[3]) : "r"(addr));
}
__device__ __forceinline__ void mma_f16(float* d, const uint32_t* a, uint2 b) {
    asm volatile(
        "mma.sync.aligned.m16n8k16.row.col.f32.f16.f16.f32 "
        "{%0,%1,%2,%3}, {%4,%5,%6,%7}, {%8,%9}, {%0,%1,%2,%3};"
        : "+f"(d[0]), "+f"(d[1]), "+f"(d[2]), "+f"(d[3])
        : "r"(a[0]), "r"(a[1]), "r"(a[2]), "r"(a[3]), "r"(b.x), "r"(b.y));
}

// ---------------------------------------------------------------------------
// prepA: cluster map + folded first-layer bias g_b1
// ---------------------------------------------------------------------------
__global__ void prepA_kernel(const int* __restrict__ clusters,
                             const float* __restrict__ bg,
                             const float* __restrict__ bs) {
    int t = threadIdx.x;
    if (t < NC) {
        int s = t / KCLUS, k = t % KCLUS;
        int c = clusters[t];
        g_cls_s[c] = s;
        g_cls_k[c] = k;
    }
    __syncthreads();
    if (t < NC) {
        int s = g_cls_s[t], k = g_cls_k[t];
        float bsum = 0.f;
        #pragma unroll
        for (int sp = 0; sp < SSPEC; sp++) bsum += bs[sp * (KCLUS + 1) + KCLUS];
        g_b1[t] = bg[t] + bs[s * (KCLUS + 1) + k] +
                  (bsum - bs[s * (KCLUS + 1) + KCLUS]) * (1.0f / (NC - KCLUS));
    }
}

// ---------------------------------------------------------------------------
// prepC (fused): fold W1[d][:] on the fly, then Weff[d][n] = W1[d]·Wc[:,n],
// stored as fp16 directly into the mma fragment image.
// 512 blocks (d) x 104 threads (n).
// ---------------------------------------------------------------------------
__global__ void prepC_kernel(const float* __restrict__ Wg,
                             const float* __restrict__ Ws,
                             const float* __restrict__ Wc) {
    __shared__ float w1row[NC];
    int d = blockIdx.x;
    int n = threadIdx.x;

    float dsum = 0.f;
    #pragma unroll
    for (int sp = 0; sp < SSPEC; sp++)
        dsum += Ws[sp * DDIM * (KCLUS + 1) + d * (KCLUS + 1) + KCLUS];
    if (n < NC) {
        int s = g_cls_s[n], k = g_cls_k[n];
        w1row[n] = Wg[d * NC + n] + Ws[s * DDIM * (KCLUS + 1) + d * (KCLUS + 1) + k] +
                   (dsum - Ws[s * DDIM * (KCLUS + 1) + d * (KCLUS + 1) + KCLUS]) *
                       (1.0f / (NC - KCLUS));
    }
    __syncthreads();

    float acc = 0.f;
    if (n < NC) {
        #pragma unroll 4
        for (int t = 0; t < NC; t++)
            acc += w1row[t] * Wc[t * NC + n];
    }
    // fragment index for element (d, n):
    //   ks = d>>4, r = d&15, reg = r>>3, lane = (n&7)*4 + ((r&7)>>1), par = d&1
    int ks = d >> 4, r = d & 15;
    int lane = ((n & 7) << 2) | ((r & 7) >> 1);
    int idx = (((ks * NTILES + (n >> 3)) * 32 + lane) << 2) | ((r >> 3) << 1) | (d & 1);
    unsigned short* bu = (unsigned short*)g_Bfrag;
    bu[idx] = __half_as_ushort(__float2half_rn(acc));
}

// ---------------------------------------------------------------------------
// prepD: beff = b1 @ Wc + bc  (one block per output col, warp-parallel dot)
// ---------------------------------------------------------------------------
__global__ void prepD_kernel(const float* __restrict__ Wc,
                             const float* __restrict__ bc) {
    int c = blockIdx.x;
    int lane = threadIdx.x;
    float s = 0.f;
    if (c < NC) {
        #pragma unroll
        for (int k = lane; k < NC; k += 32)
            s += g_b1[k] * Wc[k * NC + c];
    }
    #pragma unroll
    for (int o = 16; o > 0; o >>= 1)
        s += __shfl_xor_sync(0xFFFFFFFFu, s, o);
    if (lane == 0)
        g_beff[c] = (c < NC) ? (s + bc[c]) : 0.f;
}

// ---------------------------------------------------------------------------
// Main GEMM: out = relu(x @ Weff + beff), fp16 mma.sync, single W plane.
// TILE_M=128, 8 warps: warp grid 4(M) x 2(N); warp tile m32 x n56/n48.
// R13 structure (proven 105.4us) + R15 change: per-CTA K-chunk order rotated
// by (bid & 7). Co-resident CTAs (bids 148 apart; 148%8=4) run anti-phased,
// so one CTA's convert/LSU phase overlaps the other's MMA phase instead of
// convoying. FP32 accumulation is order-independent to rounding.
// ---------------------------------------------------------------------------
__global__ __launch_bounds__(THREADS, 2)
void gemm_main_kernel(const float* __restrict__ x, float* __restrict__ out) {
    extern __shared__ unsigned char smem_raw[];
    uint32_t sb0 = cvta_smem(smem_raw);
    uint32_t sb = (sb0 + 1023u) & ~1023u;
    unsigned char* smem = smem_raw + (sb - sb0);

    const uint32_t XS = sb + 1024;          // 2 x [128][64] f32 staging
    float* xs = (float*)(smem + 1024);

    const int tid  = threadIdx.x;
    const int wid  = tid >> 5;
    const int lane = tid & 31;
    const int wm   = wid >> 1;              // 0..3 -> m32 tile
    const int wn   = wid & 1;               // 0..1 -> n half (7 / 6 tiles)
    const int jmax = wn ? 6 : 7;

    const int rbase = tid >> 4;             // row for i=0 (0..15)
    const int q     = tid & 15;             // float4 column index

    const int rot = blockIdx.x & 7;         // per-CTA chunk-order rotation

    const float* xt = x + (size_t)blockIdx.x * TILE_M * DDIM;
    const float* xrow = xt + (size_t)rbase * DDIM + q * 4;

    float acc[2][7][4];
    #pragma unroll
    for (int mt = 0; mt < 2; mt++)
        #pragma unroll
        for (int j = 0; j < 7; j++)
            #pragma unroll
            for (int qq = 0; qq < 4; qq++) acc[mt][j][qq] = 0.f;

    // prologue: stage chunk rot (logical 0) into staging buf 0
    #pragma unroll
    for (int i = 0; i < 8; i++) {
        int r = rbase + i * 16;
        cp_async16(XS + (uint32_t)(r * 64 + q * 4) * 4,
                   xrow + (size_t)i * 16 * DDIM + rot * KC);
    }
    asm volatile("cp.async.commit_group;" ::: "memory");

    for (int ch = 0; ch < NCHUNK; ch++) {
        const int mc = (ch + rot) & 7;      // mapped (physical) chunk

        // ---- prefetch B fragments for ks=0 of this chunk (hides under
        //      convert + barrier; consumed in the MMA phase below) ----
        const uint2* bbase = g_Bfrag + (size_t)(mc * 4 * NTILES + wn * 7) * 32 + lane;
        uint2 bcur[7];
        #pragma unroll
        for (int j = 0; j < 7; j++)
            if (j < jmax) bcur[j] = bbase[j * 32];

        if (ch + 1 < NCHUNK) {
            const int mn = (ch + 1 + rot) & 7;
            uint32_t bufoff = (uint32_t)((ch + 1) & 1) * XS_BUF;
            const float* xn = xrow + mn * KC;
            #pragma unroll
            for (int i = 0; i < 8; i++) {
                int r = rbase + i * 16;
                cp_async16(XS + bufoff + (uint32_t)(r * 64 + q * 4) * 4,
                           xn + (size_t)i * 16 * DDIM);
            }
            asm volatile("cp.async.commit_group;" ::: "memory");
            asm volatile("cp.async.wait_group 1;" ::: "memory");
        } else {
            asm volatile("cp.async.wait_group 0;" ::: "memory");
        }
        // staging slots are written and read by the same thread: no sync needed

        // ---- convert staged fp32 -> fp16, swizzled STS into A[ch&1] ----
        const float* xb = xs + (ch & 1) * (XS_BUF / 4);
        uint32_t abase = A_OFF + (uint32_t)(ch & 1) * A_BUF;
        #pragma unroll
        for (int i = 0; i < 8; i++) {
            int r = rbase + i * 16;
            float4 v = *(const float4*)(xb + r * 64 + q * 4);
            __half2 p01 = __floats2half2_rn(v.x, v.y);
            __half2 p23 = __floats2half2_rn(v.z, v.w);
            uint32_t off = sw128((uint32_t)(r * 128 + q * 8));
            *(uint2*)(smem + abase + off) =
                make_uint2(*(uint32_t*)&p01, *(uint32_t*)&p23);
        }
        __syncthreads();

        // ---- MMA over 4 k16 steps, B register-pipelined ----
        const uint32_t AT = sb + abase;
        #pragma unroll
        for (int ks = 0; ks < 4; ks++) {
            // A fragments first: LDSM latency overlaps the bnxt prefetch
            uint32_t a[2][4];
            #pragma unroll
            for (int mt = 0; mt < 2; mt++) {
                int row  = wm * 32 + mt * 16 + ((lane >> 3) & 1) * 8 + (lane & 7);
                int half = lane >> 4;
                uint32_t off = sw128((uint32_t)(row * 128 + ks * 32 + half * 16));
                ldmatrix_x4(a[mt], AT + off);
            }
            // prefetch B for ks+1 before issuing this step's HMMAs
            uint2 bnxt[7];
            if (ks < 3) {
                const uint2* bp = bbase + (size_t)(ks + 1) * NTILES * 32;
                #pragma unroll
                for (int j = 0; j < 7; j++)
                    if (j < jmax) bnxt[j] = bp[j * 32];
            }
            #pragma unroll
            for (int j = 0; j < 7; j++) {
                if (j < jmax) {
                    mma_f16(acc[0][j], a[0], bcur[j]);
                    mma_f16(acc[1][j], a[1], bcur[j]);
                }
            }
            #pragma unroll
            for (int j = 0; j < 7; j++)
                if (j < jmax && ks < 3) bcur[j] = bnxt[j];
        }
        // single barrier per chunk: barrier(ch+1) orders MMA(ch) before
        // STS(ch+2) into the same A buffer (transitive WAR protection).
    }

    // ---- epilogue: bias + relu + direct STG ----
    const int g  = lane >> 2;
    const int tq = lane & 3;
    const int mrow = blockIdx.x * TILE_M + wm * 32;
    #pragma unroll
    for (int mt = 0; mt < 2; mt++) {
        #pragma unroll
        for (int j = 0; j < 7; j++) {
            if (j < jmax) {
                int c = wn * 56 + j * 8 + tq * 2;
                if (c < NC) {
                    float2 bv = *(const float2*)&g_beff[c];
                    int r0 = mrow + mt * 16 + g;
                    float v0 = acc[mt][j][0] + bv.x;
                    float v1 = acc[mt][j][1] + bv.y;
                    float v2 = acc[mt][j][2] + bv.x;
                    float v3 = acc[mt][j][3] + bv.y;
                    float2 o0 = make_float2(v0 > 0.f ? v0 : 0.f, v1 > 0.f ? v1 : 0.f);
                    float2 o1 = make_float2(v2 > 0.f ? v2 : 0.f, v3 > 0.f ? v3 : 0.f);
                    *(float2*)(out + (size_t)r0 * NC + c)       = o0;
                    *(float2*)(out + (size_t)(r0 + 8) * NC + c) = o1;
                }
            }
        }
    }
}

// ---------------------------------------------------------------------------
// Launch
// ---------------------------------------------------------------------------
extern "C" void kernel_launch(void* const* d_in, const int* in_sizes, int n_in,
                              void* d_out, int out_size) {
    const float* x        = (const float*)d_in[0];
    const float* Wg       = (const float*)d_in[1];
    const float* bg       = (const float*)d_in[2];
    const float* Ws       = (const float*)d_in[3];
    const float* bs       = (const float*)d_in[4];
    const float* Wc       = (const float*)d_in[5];
    const float* bc       = (const float*)d_in[6];
    const int*   clusters = (const int*)d_in[7];
    float* out = (float*)d_out;

    int Btot = in_sizes[0] / DDIM;      // 131072
    int grid = Btot / TILE_M;           // 1024

    cudaFuncSetAttribute(gemm_main_kernel,
                         cudaFuncAttributeMaxDynamicSharedMemorySize, SMEM_DYN);

    prepA_kernel<<<1, 128>>>(clusters, bg, bs);
    prepD_kernel<<<NPAD, 32>>>(Wc, bc);
    prepC_kernel<<<DDIM, NPAD>>>(Wg, Ws, Wc);
    gemm_main_kernel<<<grid, THREADS, SMEM_DYN>>>(x, out);
}